// round 1
// baseline (speedup 1.0000x reference)
#include <cuda_runtime.h>

#define CC   512
#define NN   4096          // 64*64
#define BB   2
#define GRPS 32
#define CPG  16            // channels per group
#define EPSF 1e-5f

// ---------------- scratch (device globals: allocation-free) ----------------
__device__ float g_hn[BB * CC * NN];   // group-normed input   [b][c][n]
__device__ float g_q [BB * CC * NN];   // q                    [b][c][n]
__device__ float g_k [BB * CC * NN];   // k                    [b][c][n]
__device__ float g_v [BB * CC * NN];   // v                    [b][c][n]
__device__ float g_S [BB * (size_t)NN * NN]; // scores/probs   [b][q][k]  (134 MB)
__device__ float g_o [BB * CC * NN];   // attention output     [b][c][n]

// ---------------- GroupNorm -------------------------------------------------
// one block per (b, group); 1024 threads; two passes (pass2 hits L2)
__global__ __launch_bounds__(1024)
void groupnorm_kernel(const float* __restrict__ x,
                      const float* __restrict__ gw,
                      const float* __restrict__ gb) {
    const int bg = blockIdx.x;
    const int b  = bg / GRPS, g = bg % GRPS;
    const size_t base = ((size_t)b * CC + (size_t)g * CPG) * NN;
    const float4* __restrict__ xp4 = (const float4*)(x + base);
    float4* __restrict__ hp4 = (float4*)(g_hn + base);
    const int t = threadIdx.x;
    const int TOT4 = (CPG * NN) / 4;       // 16384 float4

    float s = 0.f, s2 = 0.f;
    for (int i = t; i < TOT4; i += 1024) {
        float4 v = xp4[i];
        s  += v.x + v.y + v.z + v.w;
        s2 += v.x * v.x + v.y * v.y + v.z * v.z + v.w * v.w;
    }
    __shared__ float r1[32], r2[32];
    #pragma unroll
    for (int o = 16; o; o >>= 1) {
        s  += __shfl_xor_sync(~0u, s, o);
        s2 += __shfl_xor_sync(~0u, s2, o);
    }
    const int wid = t >> 5, lid = t & 31;
    if (lid == 0) { r1[wid] = s; r2[wid] = s2; }
    __syncthreads();
    if (wid == 0) {
        s = r1[lid]; s2 = r2[lid];
        #pragma unroll
        for (int o = 16; o; o >>= 1) {
            s  += __shfl_xor_sync(~0u, s, o);
            s2 += __shfl_xor_sync(~0u, s2, o);
        }
        if (lid == 0) { r1[0] = s; r2[0] = s2; }
    }
    __syncthreads();
    const float invN = 1.0f / (float)(CPG * NN);
    const float mean = r1[0] * invN;
    const float var  = r2[0] * invN - mean * mean;
    const float istd = rsqrtf(var + EPSF);

    for (int i = t; i < TOT4; i += 1024) {
        const int c = g * CPG + ((i * 4) >> 12);      // /NN
        const float sc = gw[c] * istd;
        const float sh = gb[c] - mean * sc;
        float4 v = xp4[i];
        v.x = v.x * sc + sh;  v.y = v.y * sc + sh;
        v.z = v.z * sc + sh;  v.w = v.w * sc + sh;
        hp4[i] = v;
    }
}

// ---------------- fused QKV GEMM -------------------------------------------
// out[o][n] = sum_c W[o][c] * hn[c][n] + bias[o]
// A: row-major (K contig) -> transposed smem store; B: K rows, N contig -> direct
__global__ __launch_bounds__(256)
void sgemm_qkv(const float* __restrict__ qw, const float* __restrict__ qb,
               const float* __restrict__ kw, const float* __restrict__ kb,
               const float* __restrict__ vw, const float* __restrict__ vb) {
    const int BM = 128, BN = 128, BK = 16;
    __shared__ float As[BK][BM];
    __shared__ float Bs[BK][BN];
    const int b  = blockIdx.z;
    const int mt = blockIdx.y;            // 0..11
    const int which = mt >> 2;
    const float* __restrict__ W    = which == 0 ? qw : which == 1 ? kw : vw;
    const float* __restrict__ bias = which == 0 ? qb : which == 1 ? kb : vb;
    float* __restrict__ out = (which == 0 ? g_q : which == 1 ? g_k : g_v) + (size_t)b * CC * NN;
    const float* __restrict__ Bm = g_hn + (size_t)b * CC * NN;
    const int m0 = (mt & 3) * BM;
    const int n0 = blockIdx.x * BN;

    const int t = threadIdx.x;
    const int tx = t & 15, ty = t >> 4;
    float acc[8][8] = {};

    for (int kc = 0; kc < CC; kc += BK) {
        #pragma unroll
        for (int l = 0; l < 2; l++) {
            int i = t + l * 256;
            int row = i >> 2, c4 = (i & 3) * 4;
            float4 a4 = *(const float4*)&W[(size_t)(m0 + row) * CC + kc + c4];
            As[c4 + 0][row] = a4.x; As[c4 + 1][row] = a4.y;
            As[c4 + 2][row] = a4.z; As[c4 + 3][row] = a4.w;
            int rb = i >> 5, cb = (i & 31) * 4;
            *(float4*)&Bs[rb][cb] = *(const float4*)&Bm[(size_t)(kc + rb) * NN + n0 + cb];
        }
        __syncthreads();
        #pragma unroll
        for (int kk = 0; kk < BK; kk++) {
            float a[8], bb[8];
            #pragma unroll
            for (int i = 0; i < 8; i++) a[i] = As[kk][ty * 8 + i];
            #pragma unroll
            for (int j = 0; j < 8; j++) bb[j] = Bs[kk][tx * 8 + j];
            #pragma unroll
            for (int i = 0; i < 8; i++)
                #pragma unroll
                for (int j = 0; j < 8; j++)
                    acc[i][j] += a[i] * bb[j];
        }
        __syncthreads();
    }
    #pragma unroll
    for (int i = 0; i < 8; i++) {
        const int m = m0 + ty * 8 + i;
        const float bi = bias[m];
        #pragma unroll
        for (int j = 0; j < 8; j += 4) {
            float4 r = make_float4(acc[i][j] + bi, acc[i][j + 1] + bi,
                                   acc[i][j + 2] + bi, acc[i][j + 3] + bi);
            *(float4*)&out[(size_t)m * NN + n0 + tx * 8 + j] = r;
        }
    }
}

// ---------------- scores: S[q][k] = scale * sum_c Q[c][q] K[c][k] ----------
// both operands K(=c)-rows, N contig -> direct smem loads
__global__ __launch_bounds__(256)
void sgemm_scores(float scale) {
    const int BM = 128, BN = 128, BK = 16;
    __shared__ float As[BK][BM];
    __shared__ float Bs[BK][BN];
    const int b  = blockIdx.z;
    const int m0 = blockIdx.y * BM;       // q
    const int n0 = blockIdx.x * BN;       // k
    const float* __restrict__ Q = g_q + (size_t)b * CC * NN;
    const float* __restrict__ K = g_k + (size_t)b * CC * NN;
    float* __restrict__ S = g_S + (size_t)b * NN * NN;

    const int t = threadIdx.x;
    const int tx = t & 15, ty = t >> 4;
    float acc[8][8] = {};

    for (int kc = 0; kc < CC; kc += BK) {
        #pragma unroll
        for (int l = 0; l < 2; l++) {
            int i = t + l * 256;
            int row = i >> 5, c4 = (i & 31) * 4;
            *(float4*)&As[row][c4] = *(const float4*)&Q[(size_t)(kc + row) * NN + m0 + c4];
            *(float4*)&Bs[row][c4] = *(const float4*)&K[(size_t)(kc + row) * NN + n0 + c4];
        }
        __syncthreads();
        #pragma unroll
        for (int kk = 0; kk < BK; kk++) {
            float a[8], bb[8];
            #pragma unroll
            for (int i = 0; i < 8; i++) a[i] = As[kk][ty * 8 + i];
            #pragma unroll
            for (int j = 0; j < 8; j++) bb[j] = Bs[kk][tx * 8 + j];
            #pragma unroll
            for (int i = 0; i < 8; i++)
                #pragma unroll
                for (int j = 0; j < 8; j++)
                    acc[i][j] += a[i] * bb[j];
        }
        __syncthreads();
    }
    #pragma unroll
    for (int i = 0; i < 8; i++) {
        const size_t roff = (size_t)(m0 + ty * 8 + i) * NN;
        #pragma unroll
        for (int j = 0; j < 8; j += 4) {
            float4 r = make_float4(acc[i][j] * scale, acc[i][j + 1] * scale,
                                   acc[i][j + 2] * scale, acc[i][j + 3] * scale);
            *(float4*)&S[roff + n0 + tx * 8 + j] = r;
        }
    }
}

// ---------------- row softmax over 4096 ------------------------------------
__global__ __launch_bounds__(256)
void softmax_kernel() {
    __shared__ float sh[8];
    float* __restrict__ row = g_S + (size_t)blockIdx.x * NN;
    const int t = threadIdx.x;
    float4 v[4];
    float m = -3.4e38f;
    #pragma unroll
    for (int i = 0; i < 4; i++) {
        v[i] = ((float4*)row)[t + i * 256];
        m = fmaxf(m, fmaxf(fmaxf(v[i].x, v[i].y), fmaxf(v[i].z, v[i].w)));
    }
    #pragma unroll
    for (int o = 16; o; o >>= 1) m = fmaxf(m, __shfl_xor_sync(~0u, m, o));
    if ((t & 31) == 0) sh[t >> 5] = m;
    __syncthreads();
    m = fmaxf(fmaxf(fmaxf(sh[0], sh[1]), fmaxf(sh[2], sh[3])),
              fmaxf(fmaxf(sh[4], sh[5]), fmaxf(sh[6], sh[7])));
    float s = 0.f;
    #pragma unroll
    for (int i = 0; i < 4; i++) {
        v[i].x = __expf(v[i].x - m); v[i].y = __expf(v[i].y - m);
        v[i].z = __expf(v[i].z - m); v[i].w = __expf(v[i].w - m);
        s += v[i].x + v[i].y + v[i].z + v[i].w;
    }
    #pragma unroll
    for (int o = 16; o; o >>= 1) s += __shfl_xor_sync(~0u, s, o);
    __syncthreads();
    if ((t & 31) == 0) sh[t >> 5] = s;
    __syncthreads();
    s = sh[0] + sh[1] + sh[2] + sh[3] + sh[4] + sh[5] + sh[6] + sh[7];
    const float inv = 1.0f / s;
    #pragma unroll
    for (int i = 0; i < 4; i++) {
        v[i].x *= inv; v[i].y *= inv; v[i].z *= inv; v[i].w *= inv;
        ((float4*)row)[t + i * 256] = v[i];
    }
}

// ---------------- O = V @ P^T : out[c][q] = sum_k V[c][k] P[q][k] ----------
// both tiles K(=k)-contiguous -> transposed smem stores
__global__ __launch_bounds__(256)
void sgemm_out() {
    const int BM = 128, BN = 128, BK = 16;
    __shared__ float As[BK][BM];   // [kk][c]
    __shared__ float Bs[BK][BN];   // [kk][q]
    const int b  = blockIdx.z;
    const int m0 = blockIdx.y * BM;   // c
    const int n0 = blockIdx.x * BN;   // q
    const float* __restrict__ V = g_v + (size_t)b * CC * NN;
    const float* __restrict__ P = g_S + (size_t)b * NN * NN;
    float* __restrict__ O = g_o + (size_t)b * CC * NN;

    const int t = threadIdx.x;
    const int tx = t & 15, ty = t >> 4;
    float acc[8][8] = {};

    for (int kc = 0; kc < NN; kc += BK) {
        #pragma unroll
        for (int l = 0; l < 2; l++) {
            int i = t + l * 256;
            int row = i >> 2, c4 = (i & 3) * 4;
            float4 a4 = *(const float4*)&V[(size_t)(m0 + row) * NN + kc + c4];
            As[c4 + 0][row] = a4.x; As[c4 + 1][row] = a4.y;
            As[c4 + 2][row] = a4.z; As[c4 + 3][row] = a4.w;
            float4 p4 = *(const float4*)&P[(size_t)(n0 + row) * NN + kc + c4];
            Bs[c4 + 0][row] = p4.x; Bs[c4 + 1][row] = p4.y;
            Bs[c4 + 2][row] = p4.z; Bs[c4 + 3][row] = p4.w;
        }
        __syncthreads();
        #pragma unroll
        for (int kk = 0; kk < BK; kk++) {
            float a[8], bb[8];
            #pragma unroll
            for (int i = 0; i < 8; i++) a[i] = As[kk][ty * 8 + i];
            #pragma unroll
            for (int j = 0; j < 8; j++) bb[j] = Bs[kk][tx * 8 + j];
            #pragma unroll
            for (int i = 0; i < 8; i++)
                #pragma unroll
                for (int j = 0; j < 8; j++)
                    acc[i][j] += a[i] * bb[j];
        }
        __syncthreads();
    }
    #pragma unroll
    for (int i = 0; i < 8; i++) {
        const size_t roff = (size_t)(m0 + ty * 8 + i) * NN;
        #pragma unroll
        for (int j = 0; j < 8; j += 4) {
            float4 r = make_float4(acc[i][j], acc[i][j + 1], acc[i][j + 2], acc[i][j + 3]);
            *(float4*)&O[roff + n0 + tx * 8 + j] = r;
        }
    }
}

// ---------------- proj + bias + residual -----------------------------------
__global__ __launch_bounds__(256)
void sgemm_proj(const float* __restrict__ pw, const float* __restrict__ pb,
                const float* __restrict__ x, float* __restrict__ out) {
    const int BM = 128, BN = 128, BK = 16;
    __shared__ float As[BK][BM];
    __shared__ float Bs[BK][BN];
    const int b  = blockIdx.z;
    const int m0 = blockIdx.y * BM;
    const int n0 = blockIdx.x * BN;
    const float* __restrict__ Bm = g_o + (size_t)b * CC * NN;
    const float* __restrict__ xr = x + (size_t)b * CC * NN;
    float* __restrict__ op = out + (size_t)b * CC * NN;

    const int t = threadIdx.x;
    const int tx = t & 15, ty = t >> 4;
    float acc[8][8] = {};

    for (int kc = 0; kc < CC; kc += BK) {
        #pragma unroll
        for (int l = 0; l < 2; l++) {
            int i = t + l * 256;
            int row = i >> 2, c4 = (i & 3) * 4;
            float4 a4 = *(const float4*)&pw[(size_t)(m0 + row) * CC + kc + c4];
            As[c4 + 0][row] = a4.x; As[c4 + 1][row] = a4.y;
            As[c4 + 2][row] = a4.z; As[c4 + 3][row] = a4.w;
            int rb = i >> 5, cb = (i & 31) * 4;
            *(float4*)&Bs[rb][cb] = *(const float4*)&Bm[(size_t)(kc + rb) * NN + n0 + cb];
        }
        __syncthreads();
        #pragma unroll
        for (int kk = 0; kk < BK; kk++) {
            float a[8], bb[8];
            #pragma unroll
            for (int i = 0; i < 8; i++) a[i] = As[kk][ty * 8 + i];
            #pragma unroll
            for (int j = 0; j < 8; j++) bb[j] = Bs[kk][tx * 8 + j];
            #pragma unroll
            for (int i = 0; i < 8; i++)
                #pragma unroll
                for (int j = 0; j < 8; j++)
                    acc[i][j] += a[i] * bb[j];
        }
        __syncthreads();
    }
    #pragma unroll
    for (int i = 0; i < 8; i++) {
        const int m = m0 + ty * 8 + i;
        const float bi = pb[m];
        const size_t roff = (size_t)m * NN;
        #pragma unroll
        for (int j = 0; j < 8; j += 4) {
            const size_t off = roff + n0 + tx * 8 + j;
            float4 xv = *(const float4*)&xr[off];
            float4 r = make_float4(acc[i][j]     + bi + xv.x,
                                   acc[i][j + 1] + bi + xv.y,
                                   acc[i][j + 2] + bi + xv.z,
                                   acc[i][j + 3] + bi + xv.w);
            *(float4*)&op[off] = r;
        }
    }
}

// ---------------- launch -----------------------------------------------------
extern "C" void kernel_launch(void* const* d_in, const int* in_sizes, int n_in,
                              void* d_out, int out_size) {
    const float* x      = (const float*)d_in[0];
    const float* gn_w   = (const float*)d_in[1];
    const float* gn_b   = (const float*)d_in[2];
    const float* q_w    = (const float*)d_in[3];
    const float* q_b    = (const float*)d_in[4];
    const float* k_w    = (const float*)d_in[5];
    const float* k_b    = (const float*)d_in[6];
    const float* v_w    = (const float*)d_in[7];
    const float* v_b    = (const float*)d_in[8];
    const float* proj_w = (const float*)d_in[9];
    const float* proj_b = (const float*)d_in[10];
    float* out = (float*)d_out;

    groupnorm_kernel<<<BB * GRPS, 1024>>>(x, gn_w, gn_b);
    sgemm_qkv<<<dim3(NN / 128, 12, BB), 256>>>(q_w, q_b, k_w, k_b, v_w, v_b);
    const float scale = 0.044194173824159216f;   // 512^-0.5
    sgemm_scores<<<dim3(NN / 128, NN / 128, BB), 256>>>(scale);
    softmax_kernel<<<BB * NN, 256>>>();
    sgemm_out<<<dim3(NN / 128, CC / 128, BB), 256>>>();
    sgemm_proj<<<dim3(NN / 128, CC / 128, BB), 256>>>(proj_w, proj_b, x, out);
}

// round 2
// speedup vs baseline: 2.1388x; 2.1388x over previous
#include <cuda_runtime.h>
#include <cstdint>

#define CC   512
#define NN   4096          // 64*64
#define BB   2
#define GRPS 32
#define CPG  16
#define EPSF 1e-5f

#define BK   32
#define BMP  132           // 128 + 4 pad

// ---------------- scratch (device globals: allocation-free) ----------------
__device__ float g_hn[BB * CC * NN];
__device__ float g_q [BB * CC * NN];
__device__ float g_k [BB * CC * NN];
__device__ float g_v [BB * CC * NN];
__device__ float g_S [BB * (size_t)NN * NN];   // 134 MB
__device__ float g_o [BB * CC * NN];

// ---------------- tf32 helper ----------------------------------------------
__device__ __forceinline__ float f2tf(float x) {
    uint32_t r;
    asm("cvt.rna.tf32.f32 %0, %1;" : "=r"(r) : "f"(x));
    return __uint_as_float(r);
}

// ---------------- GroupNorm (unchanged) -------------------------------------
__global__ __launch_bounds__(1024)
void groupnorm_kernel(const float* __restrict__ x,
                      const float* __restrict__ gw,
                      const float* __restrict__ gb) {
    const int bg = blockIdx.x;
    const int b  = bg / GRPS, g = bg % GRPS;
    const size_t base = ((size_t)b * CC + (size_t)g * CPG) * NN;
    const float4* __restrict__ xp4 = (const float4*)(x + base);
    float4* __restrict__ hp4 = (float4*)(g_hn + base);
    const int t = threadIdx.x;
    const int TOT4 = (CPG * NN) / 4;

    float s = 0.f, s2 = 0.f;
    for (int i = t; i < TOT4; i += 1024) {
        float4 v = xp4[i];
        s  += v.x + v.y + v.z + v.w;
        s2 += v.x * v.x + v.y * v.y + v.z * v.z + v.w * v.w;
    }
    __shared__ float r1[32], r2[32];
    #pragma unroll
    for (int o = 16; o; o >>= 1) {
        s  += __shfl_xor_sync(~0u, s, o);
        s2 += __shfl_xor_sync(~0u, s2, o);
    }
    const int wid = t >> 5, lid = t & 31;
    if (lid == 0) { r1[wid] = s; r2[wid] = s2; }
    __syncthreads();
    if (wid == 0) {
        s = r1[lid]; s2 = r2[lid];
        #pragma unroll
        for (int o = 16; o; o >>= 1) {
            s  += __shfl_xor_sync(~0u, s, o);
            s2 += __shfl_xor_sync(~0u, s2, o);
        }
        if (lid == 0) { r1[0] = s; r2[0] = s2; }
    }
    __syncthreads();
    const float invN = 1.0f / (float)(CPG * NN);
    const float mean = r1[0] * invN;
    const float var  = r2[0] * invN - mean * mean;
    const float istd = rsqrtf(var + EPSF);

    for (int i = t; i < TOT4; i += 1024) {
        const int c = g * CPG + ((i * 4) >> 12);
        const float sc = gw[c] * istd;
        const float sh = gb[c] - mean * sc;
        float4 v = xp4[i];
        v.x = v.x * sc + sh;  v.y = v.y * sc + sh;
        v.z = v.z * sc + sh;  v.w = v.w * sc + sh;
        hp4[i] = v;
    }
}

// ---------------- tf32 mma inner block --------------------------------------
// As[k][m], Bs[k][n] (both [BK][BMP]); warp tile 64x32; acc[mt][nt][4]
__device__ __forceinline__ void mma_block(const float (*As)[BMP], const float (*Bs)[BMP],
                                          float (&acc)[4][4][4], int wm, int wn, int lane) {
    const int j = lane & 3, g = lane >> 2;
    #pragma unroll
    for (int kb = 0; kb < 4; kb++) {
        const int k0 = kb * 8 + j;
        uint32_t a[4][4], bf[4][2];
        #pragma unroll
        for (int mt = 0; mt < 4; mt++) {
            const int m = wm + mt * 16 + g;
            a[mt][0] = __float_as_uint(As[k0    ][m    ]);
            a[mt][1] = __float_as_uint(As[k0    ][m + 8]);
            a[mt][2] = __float_as_uint(As[k0 + 4][m    ]);
            a[mt][3] = __float_as_uint(As[k0 + 4][m + 8]);
        }
        #pragma unroll
        for (int nt = 0; nt < 4; nt++) {
            const int n = wn + nt * 8 + g;
            bf[nt][0] = __float_as_uint(Bs[k0    ][n]);
            bf[nt][1] = __float_as_uint(Bs[k0 + 4][n]);
        }
        #pragma unroll
        for (int mt = 0; mt < 4; mt++)
            #pragma unroll
            for (int nt = 0; nt < 4; nt++)
                asm volatile(
                    "mma.sync.aligned.m16n8k8.row.col.f32.tf32.tf32.f32 "
                    "{%0,%1,%2,%3}, {%4,%5,%6,%7}, {%8,%9}, {%0,%1,%2,%3};"
                    : "+f"(acc[mt][nt][0]), "+f"(acc[mt][nt][1]),
                      "+f"(acc[mt][nt][2]), "+f"(acc[mt][nt][3])
                    : "r"(a[mt][0]), "r"(a[mt][1]), "r"(a[mt][2]), "r"(a[mt][3]),
                      "r"(bf[nt][0]), "r"(bf[nt][1]));
    }
}

// stage A from k-contiguous global rows: G[m][k] -> As[k][m]   (transposed scalar writes)
__device__ __forceinline__ void stage_kcontig(float (*As)[BMP], const float* __restrict__ G,
                                              int m0, int kc, int ld, int t) {
    #pragma unroll
    for (int l = 0; l < 4; l++) {
        const int i = t + l * 256;
        const int row = i >> 3, c4 = (i & 7) * 4;
        float4 a = *(const float4*)&G[(size_t)(m0 + row) * ld + kc + c4];
        As[c4 + 0][row] = f2tf(a.x);
        As[c4 + 1][row] = f2tf(a.y);
        As[c4 + 2][row] = f2tf(a.z);
        As[c4 + 3][row] = f2tf(a.w);
    }
}

// stage from n-contiguous global (k rows): G[k][n] -> Bs[k][n]  (direct float4 writes)
__device__ __forceinline__ void stage_ncontig(float (*Bs)[BMP], const float* __restrict__ G,
                                              int n0, int kc, int ld, int t) {
    #pragma unroll
    for (int l = 0; l < 4; l++) {
        const int i = t + l * 256;
        const int kr = i >> 5, n4 = (i & 31) * 4;
        float4 bv = *(const float4*)&G[(size_t)(kc + kr) * ld + n0 + n4];
        bv.x = f2tf(bv.x); bv.y = f2tf(bv.y); bv.z = f2tf(bv.z); bv.w = f2tf(bv.w);
        *(float4*)&Bs[kr][n4] = bv;
    }
}

// ---------------- fused QKV GEMM (tf32 mma) ---------------------------------
__global__ __launch_bounds__(256)
void mma_qkv(const float* __restrict__ qw, const float* __restrict__ qb,
             const float* __restrict__ kw, const float* __restrict__ kb,
             const float* __restrict__ vw, const float* __restrict__ vb) {
    __shared__ float As[BK][BMP], Bs[BK][BMP];
    const int b  = blockIdx.z;
    const int mt = blockIdx.y;
    const int which = mt >> 2;
    const float* __restrict__ W    = which == 0 ? qw : which == 1 ? kw : vw;
    const float* __restrict__ bias = which == 0 ? qb : which == 1 ? kb : vb;
    float* __restrict__ out = (which == 0 ? g_q : which == 1 ? g_k : g_v) + (size_t)b * CC * NN;
    const float* __restrict__ Bm = g_hn + (size_t)b * CC * NN;
    const int m0 = (mt & 3) * 128;
    const int n0 = blockIdx.x * 128;

    const int t = threadIdx.x, lane = t & 31, w = t >> 5;
    const int wm = (w & 1) * 64, wn = (w >> 1) * 32;
    float acc[4][4][4] = {};

    for (int kc = 0; kc < CC; kc += BK) {
        stage_kcontig(As, W, m0, kc, CC, t);
        stage_ncontig(Bs, Bm, n0, kc, NN, t);
        __syncthreads();
        mma_block(As, Bs, acc, wm, wn, lane);
        __syncthreads();
    }
    const int j = lane & 3, g = lane >> 5 ? 0 : lane >> 2;   // g = lane>>2
    #pragma unroll
    for (int mtl = 0; mtl < 4; mtl++) {
        const int r = m0 + wm + mtl * 16 + (lane >> 2);
        const float b0 = bias[r], b1 = bias[r + 8];
        #pragma unroll
        for (int nt = 0; nt < 4; nt++) {
            const int c = n0 + wn + nt * 8 + 2 * j;
            *(float2*)&out[(size_t)r * NN + c] =
                make_float2(acc[mtl][nt][0] + b0, acc[mtl][nt][1] + b0);
            *(float2*)&out[(size_t)(r + 8) * NN + c] =
                make_float2(acc[mtl][nt][2] + b1, acc[mtl][nt][3] + b1);
        }
    }
    (void)g;
}

// ---------------- scores (tf32 mma) -----------------------------------------
__global__ __launch_bounds__(256)
void mma_scores(float scale) {
    __shared__ float As[BK][BMP], Bs[BK][BMP];
    const int b  = blockIdx.z;
    const int m0 = blockIdx.y * 128;
    const int n0 = blockIdx.x * 128;
    const float* __restrict__ Q = g_q + (size_t)b * CC * NN;
    const float* __restrict__ K = g_k + (size_t)b * CC * NN;
    float* __restrict__ S = g_S + (size_t)b * NN * NN;

    const int t = threadIdx.x, lane = t & 31, w = t >> 5;
    const int wm = (w & 1) * 64, wn = (w >> 1) * 32;
    float acc[4][4][4] = {};

    for (int kc = 0; kc < CC; kc += BK) {
        stage_ncontig(As, Q, m0, kc, NN, t);   // Q[c][q] -> As[c][q]
        stage_ncontig(Bs, K, n0, kc, NN, t);   // K[c][k] -> Bs[c][k]
        __syncthreads();
        mma_block(As, Bs, acc, wm, wn, lane);
        __syncthreads();
    }
    const int j = lane & 3;
    #pragma unroll
    for (int mtl = 0; mtl < 4; mtl++) {
        const int r = m0 + wm + mtl * 16 + (lane >> 2);
        #pragma unroll
        for (int nt = 0; nt < 4; nt++) {
            const int c = n0 + wn + nt * 8 + 2 * j;
            *(float2*)&S[(size_t)r * NN + c] =
                make_float2(acc[mtl][nt][0] * scale, acc[mtl][nt][1] * scale);
            *(float2*)&S[(size_t)(r + 8) * NN + c] =
                make_float2(acc[mtl][nt][2] * scale, acc[mtl][nt][3] * scale);
        }
    }
}

// ---------------- row softmax (unchanged) ------------------------------------
__global__ __launch_bounds__(256)
void softmax_kernel() {
    __shared__ float sh[8];
    float* __restrict__ row = g_S + (size_t)blockIdx.x * NN;
    const int t = threadIdx.x;
    float4 v[4];
    float m = -3.4e38f;
    #pragma unroll
    for (int i = 0; i < 4; i++) {
        v[i] = ((float4*)row)[t + i * 256];
        m = fmaxf(m, fmaxf(fmaxf(v[i].x, v[i].y), fmaxf(v[i].z, v[i].w)));
    }
    #pragma unroll
    for (int o = 16; o; o >>= 1) m = fmaxf(m, __shfl_xor_sync(~0u, m, o));
    if ((t & 31) == 0) sh[t >> 5] = m;
    __syncthreads();
    m = fmaxf(fmaxf(fmaxf(sh[0], sh[1]), fmaxf(sh[2], sh[3])),
              fmaxf(fmaxf(sh[4], sh[5]), fmaxf(sh[6], sh[7])));
    float s = 0.f;
    #pragma unroll
    for (int i = 0; i < 4; i++) {
        v[i].x = __expf(v[i].x - m); v[i].y = __expf(v[i].y - m);
        v[i].z = __expf(v[i].z - m); v[i].w = __expf(v[i].w - m);
        s += v[i].x + v[i].y + v[i].z + v[i].w;
    }
    #pragma unroll
    for (int o = 16; o; o >>= 1) s += __shfl_xor_sync(~0u, s, o);
    __syncthreads();
    if ((t & 31) == 0) sh[t >> 5] = s;
    __syncthreads();
    s = sh[0] + sh[1] + sh[2] + sh[3] + sh[4] + sh[5] + sh[6] + sh[7];
    const float inv = 1.0f / s;
    #pragma unroll
    for (int i = 0; i < 4; i++) {
        v[i].x *= inv; v[i].y *= inv; v[i].z *= inv; v[i].w *= inv;
        ((float4*)row)[t + i * 256] = v[i];
    }
}

// ---------------- O = V @ P^T (tf32 mma) ------------------------------------
__global__ __launch_bounds__(256)
void mma_out() {
    __shared__ float As[BK][BMP], Bs[BK][BMP];
    const int b  = blockIdx.z;
    const int m0 = blockIdx.y * 128;   // c
    const int n0 = blockIdx.x * 128;   // q
    const float* __restrict__ V = g_v + (size_t)b * CC * NN;
    const float* __restrict__ P = g_S + (size_t)b * NN * NN;
    float* __restrict__ O = g_o + (size_t)b * CC * NN;

    const int t = threadIdx.x, lane = t & 31, w = t >> 5;
    const int wm = (w & 1) * 64, wn = (w >> 1) * 32;
    float acc[4][4][4] = {};

    for (int kc = 0; kc < NN; kc += BK) {
        stage_kcontig(As, V, m0, kc, NN, t);   // V[c][kk] -> As[kk][c]
        stage_kcontig(Bs, P, n0, kc, NN, t);   // P[q][kk] -> Bs[kk][q]
        __syncthreads();
        mma_block(As, Bs, acc, wm, wn, lane);
        __syncthreads();
    }
    const int j = lane & 3;
    #pragma unroll
    for (int mtl = 0; mtl < 4; mtl++) {
        const int r = m0 + wm + mtl * 16 + (lane >> 2);
        #pragma unroll
        for (int nt = 0; nt < 4; nt++) {
            const int c = n0 + wn + nt * 8 + 2 * j;
            *(float2*)&O[(size_t)r * NN + c] =
                make_float2(acc[mtl][nt][0], acc[mtl][nt][1]);
            *(float2*)&O[(size_t)(r + 8) * NN + c] =
                make_float2(acc[mtl][nt][2], acc[mtl][nt][3]);
        }
    }
}

// ---------------- proj + bias + residual (tf32 mma) --------------------------
__global__ __launch_bounds__(256)
void mma_proj(const float* __restrict__ pw, const float* __restrict__ pb,
              const float* __restrict__ x, float* __restrict__ out) {
    __shared__ float As[BK][BMP], Bs[BK][BMP];
    const int b  = blockIdx.z;
    const int m0 = blockIdx.y * 128;
    const int n0 = blockIdx.x * 128;
    const float* __restrict__ Bm = g_o + (size_t)b * CC * NN;
    const float* __restrict__ xr = x + (size_t)b * CC * NN;
    float* __restrict__ op = out + (size_t)b * CC * NN;

    const int t = threadIdx.x, lane = t & 31, w = t >> 5;
    const int wm = (w & 1) * 64, wn = (w >> 1) * 32;
    float acc[4][4][4] = {};

    for (int kc = 0; kc < CC; kc += BK) {
        stage_kcontig(As, pw, m0, kc, CC, t);
        stage_ncontig(Bs, Bm, n0, kc, NN, t);
        __syncthreads();
        mma_block(As, Bs, acc, wm, wn, lane);
        __syncthreads();
    }
    const int j = lane & 3;
    #pragma unroll
    for (int mtl = 0; mtl < 4; mtl++) {
        const int r = m0 + wm + mtl * 16 + (lane >> 2);
        const float b0 = pb[r], b1 = pb[r + 8];
        #pragma unroll
        for (int nt = 0; nt < 4; nt++) {
            const int c = n0 + wn + nt * 8 + 2 * j;
            const size_t o0 = (size_t)r * NN + c;
            const size_t o1 = (size_t)(r + 8) * NN + c;
            float2 x0 = *(const float2*)&xr[o0];
            float2 x1 = *(const float2*)&xr[o1];
            *(float2*)&op[o0] = make_float2(acc[mtl][nt][0] + b0 + x0.x,
                                            acc[mtl][nt][1] + b0 + x0.y);
            *(float2*)&op[o1] = make_float2(acc[mtl][nt][2] + b1 + x1.x,
                                            acc[mtl][nt][3] + b1 + x1.y);
        }
    }
}

// ---------------- launch ------------------------------------------------------
extern "C" void kernel_launch(void* const* d_in, const int* in_sizes, int n_in,
                              void* d_out, int out_size) {
    const float* x      = (const float*)d_in[0];
    const float* gn_w   = (const float*)d_in[1];
    const float* gn_b   = (const float*)d_in[2];
    const float* q_w    = (const float*)d_in[3];
    const float* q_b    = (const float*)d_in[4];
    const float* k_w    = (const float*)d_in[5];
    const float* k_b    = (const float*)d_in[6];
    const float* v_w    = (const float*)d_in[7];
    const float* v_b    = (const float*)d_in[8];
    const float* proj_w = (const float*)d_in[9];
    const float* proj_b = (const float*)d_in[10];
    float* out = (float*)d_out;

    groupnorm_kernel<<<BB * GRPS, 1024>>>(x, gn_w, gn_b);
    mma_qkv<<<dim3(NN / 128, 12, BB), 256>>>(q_w, q_b, k_w, k_b, v_w, v_b);
    const float scale = 0.044194173824159216f;   // 512^-0.5
    mma_scores<<<dim3(NN / 128, NN / 128, BB), 256>>>(scale);
    softmax_kernel<<<BB * NN, 256>>>();
    mma_out<<<dim3(NN / 128, CC / 128, BB), 256>>>();
    mma_proj<<<dim3(NN / 128, CC / 128, BB), 256>>>(proj_w, proj_b, x, out);
}

// round 3
// speedup vs baseline: 5.9583x; 2.7858x over previous
#include <cuda_runtime.h>
#include <cuda_bf16.h>
#include <cstdint>

#define CC   512
#define NN   4096
#define BB   2
#define GRPS 32
#define CPG  16
#define EPSF 1e-5f
#define BKE  32            // k elements per pipeline stage
#define RSTR 40            // smem row stride in bf16 (32 data + 8 pad) -> conflict-free ldmatrix

typedef __nv_bfloat16  bf16;
typedef __nv_bfloat162 bf162;

// ---------------- scratch (device globals: allocation-free) ----------------
__device__ bf16  g_hn[BB * NN * CC];            // GN output, token-major [b][n][c]
__device__ bf16  g_q [BB * NN * CC];            // [b][n][c]
__device__ bf16  g_k [BB * NN * CC];            // [b][n][c]
__device__ bf16  g_v [BB * CC * NN];            // [b][c][n]
__device__ float g_S [BB * (size_t)NN * NN];    // scores fp32 [b][q][k]
__device__ bf16  g_P [BB * (size_t)NN * NN];    // probs bf16 [b][q][k]
__device__ bf16  g_o [BB * NN * CC];            // attn out [b][q][c]
__device__ bf16  g_wq[CC * CC], g_wk[CC * CC], g_wv[CC * CC], g_wp[CC * CC];

// ---------------- weight fp32 -> bf16 ---------------------------------------
__global__ __launch_bounds__(256)
void convert_w(const float* __restrict__ qw, const float* __restrict__ kw,
               const float* __restrict__ vw, const float* __restrict__ pw) {
    const int i = blockIdx.x * 256 + threadIdx.x;     // 4 * 65536 float4 chunks
    const int which = i >> 16, j = i & 65535;
    const float* src = which == 0 ? qw : which == 1 ? kw : which == 2 ? vw : pw;
    bf16* dst = which == 0 ? g_wq : which == 1 ? g_wk : which == 2 ? g_wv : g_wp;
    float4 v = ((const float4*)src)[j];
    bf162* d2 = (bf162*)(dst + (size_t)j * 4);
    d2[0] = __floats2bfloat162_rn(v.x, v.y);
    d2[1] = __floats2bfloat162_rn(v.z, v.w);
}

// ---------------- GroupNorm -> bf16 transposed [n][c] ------------------------
__global__ __launch_bounds__(1024)
void groupnorm_kernel(const float* __restrict__ x,
                      const float* __restrict__ gw,
                      const float* __restrict__ gb) {
    const int bg = blockIdx.x;
    const int b  = bg / GRPS, g = bg % GRPS;
    const size_t base = ((size_t)b * CC + (size_t)g * CPG) * NN;
    const float4* __restrict__ xp4 = (const float4*)(x + base);
    const int t = threadIdx.x;
    const int TOT4 = (CPG * NN) / 4;

    float s = 0.f, s2 = 0.f;
    for (int i = t; i < TOT4; i += 1024) {
        float4 v = xp4[i];
        s  += v.x + v.y + v.z + v.w;
        s2 += v.x * v.x + v.y * v.y + v.z * v.z + v.w * v.w;
    }
    __shared__ float r1[32], r2[32];
    #pragma unroll
    for (int o = 16; o; o >>= 1) {
        s  += __shfl_xor_sync(~0u, s, o);
        s2 += __shfl_xor_sync(~0u, s2, o);
    }
    const int wid = t >> 5, lid = t & 31;
    if (lid == 0) { r1[wid] = s; r2[wid] = s2; }
    __syncthreads();
    if (wid == 0) {
        s = r1[lid]; s2 = r2[lid];
        #pragma unroll
        for (int o = 16; o; o >>= 1) {
            s  += __shfl_xor_sync(~0u, s, o);
            s2 += __shfl_xor_sync(~0u, s2, o);
        }
        if (lid == 0) { r1[0] = s; r2[0] = s2; }
    }
    __syncthreads();
    const float invN = 1.0f / (float)(CPG * NN);
    const float mean = r1[0] * invN;
    const float var  = r2[0] * invN - mean * mean;
    const float istd = rsqrtf(var + EPSF);

    float sc[CPG], sh[CPG];
    #pragma unroll
    for (int ci = 0; ci < CPG; ci++) {
        sc[ci] = gw[g * CPG + ci] * istd;
        sh[ci] = gb[g * CPG + ci] - mean * sc[ci];
    }
    const float* __restrict__ xs = x + base;
    bf16* __restrict__ dst = g_hn + (size_t)b * NN * CC + g * CPG;
    for (int n = t; n < NN; n += 1024) {
        alignas(16) bf162 o[8];
        #pragma unroll
        for (int ci = 0; ci < CPG; ci += 2) {
            float v0 = xs[(size_t)ci * NN + n] * sc[ci] + sh[ci];
            float v1 = xs[(size_t)(ci + 1) * NN + n] * sc[ci + 1] + sh[ci + 1];
            o[ci >> 1] = __floats2bfloat162_rn(v0, v1);
        }
        *(uint4*)&dst[(size_t)n * CC]     = *(uint4*)&o[0];
        *(uint4*)&dst[(size_t)n * CC + 8] = *(uint4*)&o[4];
    }
}

// ---------------- bf16 ldmatrix/mma GEMM core --------------------------------
// D[M][N] += A[M][K] * B[N][K]^T ; A,B bf16 K-contiguous; block 128x128, BK=32,
// 8 warps (warp tile 64x32), cp.async double buffer.
__device__ __forceinline__ void gemm_core(
    const bf16* __restrict__ A, int lda,
    const bf16* __restrict__ B, int ldb,
    int m0, int n0, int K, float (&acc)[4][4][4])
{
    __shared__ bf16 As[2][128 * RSTR];
    __shared__ bf16 Bs[2][128 * RSTR];
    const int t = threadIdx.x, lane = t & 31, w = t >> 5;
    const int wm = (w & 1) * 64, wn = (w >> 1) * 32;
    const int grp = lane >> 3, lr = lane & 7;

    // staging: 512 16B-chunks per tile, 2 per thread per tile
    const int ra = t >> 2,          ca = (t & 3) * 8;
    const int rb = (t + 256) >> 2,  cb = ((t + 256) & 3) * 8;
    const bf16* gA0 = A + (size_t)(m0 + ra) * lda + ca;
    const bf16* gA1 = A + (size_t)(m0 + rb) * lda + cb;
    const bf16* gB0 = B + (size_t)(n0 + ra) * ldb + ca;
    const bf16* gB1 = B + (size_t)(n0 + rb) * ldb + cb;

    uint32_t dA0[2], dA1[2], dB0[2], dB1[2], asb[2], bsb[2];
    #pragma unroll
    for (int s = 0; s < 2; s++) {
        dA0[s] = (uint32_t)__cvta_generic_to_shared(&As[s][ra * RSTR + ca]);
        dA1[s] = (uint32_t)__cvta_generic_to_shared(&As[s][rb * RSTR + cb]);
        dB0[s] = (uint32_t)__cvta_generic_to_shared(&Bs[s][ra * RSTR + ca]);
        dB1[s] = (uint32_t)__cvta_generic_to_shared(&Bs[s][rb * RSTR + cb]);
        asb[s] = (uint32_t)__cvta_generic_to_shared(&As[s][0]);
        bsb[s] = (uint32_t)__cvta_generic_to_shared(&Bs[s][0]);
    }
    // ldmatrix byte offsets (per warp, per fragment tile)
    int aoff[4], boff[2];
    #pragma unroll
    for (int mt = 0; mt < 4; mt++)
        aoff[mt] = ((wm + mt * 16 + (grp & 1) * 8 + lr) * RSTR + (grp >> 1) * 8) * 2;
    #pragma unroll
    for (int bt = 0; bt < 2; bt++)
        boff[bt] = ((wn + bt * 16 + (grp >> 1) * 8 + lr) * RSTR + (grp & 1) * 8) * 2;

    const int iters = K / BKE;

    auto stage = [&](int s, int kc) {
        asm volatile("cp.async.cg.shared.global [%0], [%1], 16;\n" :: "r"(dA0[s]), "l"(gA0 + kc) : "memory");
        asm volatile("cp.async.cg.shared.global [%0], [%1], 16;\n" :: "r"(dA1[s]), "l"(gA1 + kc) : "memory");
        asm volatile("cp.async.cg.shared.global [%0], [%1], 16;\n" :: "r"(dB0[s]), "l"(gB0 + kc) : "memory");
        asm volatile("cp.async.cg.shared.global [%0], [%1], 16;\n" :: "r"(dB1[s]), "l"(gB1 + kc) : "memory");
        asm volatile("cp.async.commit_group;\n" ::: "memory");
    };
    auto compute = [&](int s) {
        #pragma unroll
        for (int kk = 0; kk < 2; kk++) {
            uint32_t af[4][4], bfr[2][4];
            #pragma unroll
            for (int mt = 0; mt < 4; mt++) {
                uint32_t ad = asb[s] + aoff[mt] + kk * 32;
                asm volatile("ldmatrix.sync.aligned.m8n8.x4.shared.b16 {%0,%1,%2,%3}, [%4];\n"
                             : "=r"(af[mt][0]), "=r"(af[mt][1]), "=r"(af[mt][2]), "=r"(af[mt][3])
                             : "r"(ad));
            }
            #pragma unroll
            for (int bt = 0; bt < 2; bt++) {
                uint32_t bd = bsb[s] + boff[bt] + kk * 32;
                asm volatile("ldmatrix.sync.aligned.m8n8.x4.shared.b16 {%0,%1,%2,%3}, [%4];\n"
                             : "=r"(bfr[bt][0]), "=r"(bfr[bt][1]), "=r"(bfr[bt][2]), "=r"(bfr[bt][3])
                             : "r"(bd));
            }
            #pragma unroll
            for (int mt = 0; mt < 4; mt++)
                #pragma unroll
                for (int nt = 0; nt < 4; nt++) {
                    asm volatile(
                        "mma.sync.aligned.m16n8k16.row.col.f32.bf16.bf16.f32 "
                        "{%0,%1,%2,%3},{%4,%5,%6,%7},{%8,%9},{%0,%1,%2,%3};\n"
                        : "+f"(acc[mt][nt][0]), "+f"(acc[mt][nt][1]),
                          "+f"(acc[mt][nt][2]), "+f"(acc[mt][nt][3])
                        : "r"(af[mt][0]), "r"(af[mt][1]), "r"(af[mt][2]), "r"(af[mt][3]),
                          "r"(bfr[nt >> 1][(nt & 1) * 2]), "r"(bfr[nt >> 1][(nt & 1) * 2 + 1]));
                }
        }
    };

    stage(0, 0);
    int s = 0;
    for (int it = 0; it < iters; it++) {
        asm volatile("cp.async.wait_group 0;\n" ::: "memory");
        __syncthreads();
        if (it + 1 < iters) stage(s ^ 1, (it + 1) * BKE);
        compute(s);
        __syncthreads();
        s ^= 1;
    }
}

// ---------------- GEMM instances ---------------------------------------------
__global__ __launch_bounds__(256)
void gemm_qk(const float* __restrict__ qb, const float* __restrict__ kb) {
    const int b = blockIdx.z >> 1, which = blockIdx.z & 1;
    const bf16* A = g_hn + (size_t)b * NN * CC;
    const bf16* B = which ? g_wk : g_wq;
    bf16* D = (which ? g_k : g_q) + (size_t)b * NN * CC;
    const float* bias = which ? kb : qb;
    const int m0 = blockIdx.y * 128, n0 = blockIdx.x * 128;
    float acc[4][4][4] = {};
    gemm_core(A, CC, B, CC, m0, n0, CC, acc);
    const int lane = threadIdx.x & 31, w = threadIdx.x >> 5;
    const int wm = (w & 1) * 64, wn = (w >> 1) * 32, gq = lane >> 2, j = lane & 3;
    #pragma unroll
    for (int mt = 0; mt < 4; mt++) {
        const int r = m0 + wm + mt * 16 + gq;
        #pragma unroll
        for (int nt = 0; nt < 4; nt++) {
            const int c = n0 + wn + nt * 8 + 2 * j;
            const float b0 = bias[c], b1 = bias[c + 1];
            *(bf162*)&D[(size_t)r * CC + c] =
                __floats2bfloat162_rn(acc[mt][nt][0] + b0, acc[mt][nt][1] + b1);
            *(bf162*)&D[(size_t)(r + 8) * CC + c] =
                __floats2bfloat162_rn(acc[mt][nt][2] + b0, acc[mt][nt][3] + b1);
        }
    }
}

__global__ __launch_bounds__(256)
void gemm_v(const float* __restrict__ vb) {
    const int b = blockIdx.z;
    const bf16* A = g_wv;
    const bf16* B = g_hn + (size_t)b * NN * CC;
    bf16* D = g_v + (size_t)b * CC * NN;
    const int m0 = blockIdx.y * 128, n0 = blockIdx.x * 128;
    float acc[4][4][4] = {};
    gemm_core(A, CC, B, CC, m0, n0, CC, acc);
    const int lane = threadIdx.x & 31, w = threadIdx.x >> 5;
    const int wm = (w & 1) * 64, wn = (w >> 1) * 32, gq = lane >> 2, j = lane & 3;
    #pragma unroll
    for (int mt = 0; mt < 4; mt++) {
        const int r = m0 + wm + mt * 16 + gq;
        const float b0 = vb[r], b1 = vb[r + 8];
        #pragma unroll
        for (int nt = 0; nt < 4; nt++) {
            const int c = n0 + wn + nt * 8 + 2 * j;
            *(bf162*)&D[(size_t)r * NN + c] =
                __floats2bfloat162_rn(acc[mt][nt][0] + b0, acc[mt][nt][1] + b0);
            *(bf162*)&D[(size_t)(r + 8) * NN + c] =
                __floats2bfloat162_rn(acc[mt][nt][2] + b1, acc[mt][nt][3] + b1);
        }
    }
}

__global__ __launch_bounds__(256)
void gemm_scores(float scale) {
    const int b = blockIdx.z;
    const bf16* A = g_q + (size_t)b * NN * CC;
    const bf16* B = g_k + (size_t)b * NN * CC;
    float* S = g_S + (size_t)b * NN * NN;
    const int m0 = blockIdx.y * 128, n0 = blockIdx.x * 128;
    float acc[4][4][4] = {};
    gemm_core(A, CC, B, CC, m0, n0, CC, acc);
    const int lane = threadIdx.x & 31, w = threadIdx.x >> 5;
    const int wm = (w & 1) * 64, wn = (w >> 1) * 32, gq = lane >> 2, j = lane & 3;
    #pragma unroll
    for (int mt = 0; mt < 4; mt++) {
        const int r = m0 + wm + mt * 16 + gq;
        #pragma unroll
        for (int nt = 0; nt < 4; nt++) {
            const int c = n0 + wn + nt * 8 + 2 * j;
            *(float2*)&S[(size_t)r * NN + c] =
                make_float2(acc[mt][nt][0] * scale, acc[mt][nt][1] * scale);
            *(float2*)&S[(size_t)(r + 8) * NN + c] =
                make_float2(acc[mt][nt][2] * scale, acc[mt][nt][3] * scale);
        }
    }
}

__global__ __launch_bounds__(256)
void gemm_out() {
    const int b = blockIdx.z;
    const bf16* A = g_P + (size_t)b * NN * NN;
    const bf16* B = g_v + (size_t)b * CC * NN;
    bf16* D = g_o + (size_t)b * NN * CC;
    const int m0 = blockIdx.y * 128, n0 = blockIdx.x * 128;
    float acc[4][4][4] = {};
    gemm_core(A, NN, B, NN, m0, n0, NN, acc);
    const int lane = threadIdx.x & 31, w = threadIdx.x >> 5;
    const int wm = (w & 1) * 64, wn = (w >> 1) * 32, gq = lane >> 2, j = lane & 3;
    #pragma unroll
    for (int mt = 0; mt < 4; mt++) {
        const int r = m0 + wm + mt * 16 + gq;
        #pragma unroll
        for (int nt = 0; nt < 4; nt++) {
            const int c = n0 + wn + nt * 8 + 2 * j;
            *(bf162*)&D[(size_t)r * CC + c] =
                __floats2bfloat162_rn(acc[mt][nt][0], acc[mt][nt][1]);
            *(bf162*)&D[(size_t)(r + 8) * CC + c] =
                __floats2bfloat162_rn(acc[mt][nt][2], acc[mt][nt][3]);
        }
    }
}

__global__ __launch_bounds__(256)
void gemm_proj(const float* __restrict__ pb, const float* __restrict__ x,
               float* __restrict__ out) {
    const int b = blockIdx.z;
    const bf16* A = g_o + (size_t)b * NN * CC;
    const bf16* B = g_wp;
    const int m0 = blockIdx.y * 128, n0 = blockIdx.x * 128;
    float acc[4][4][4] = {};
    gemm_core(A, CC, B, CC, m0, n0, CC, acc);
    const int lane = threadIdx.x & 31, w = threadIdx.x >> 5;
    const int wm = (w & 1) * 64, wn = (w >> 1) * 32, gq = lane >> 2, j = lane & 3;
    const size_t bofs = (size_t)b * CC * NN;
    #pragma unroll
    for (int mt = 0; mt < 4; mt++) {
        const int r = m0 + wm + mt * 16 + gq;
        #pragma unroll
        for (int nt = 0; nt < 4; nt++) {
            const int c = n0 + wn + nt * 8 + 2 * j;
            const float b0 = pb[c], b1 = pb[c + 1];
            const size_t i00 = bofs + (size_t)c * NN + r;
            const size_t i01 = i00 + NN;          // (r, c+1)
            out[i00]     = acc[mt][nt][0] + b0 + x[i00];
            out[i01]     = acc[mt][nt][1] + b1 + x[i01];
            out[i00 + 8] = acc[mt][nt][2] + b0 + x[i00 + 8];
            out[i01 + 8] = acc[mt][nt][3] + b1 + x[i01 + 8];
        }
    }
}

// ---------------- row softmax: fp32 S -> bf16 P -------------------------------
__global__ __launch_bounds__(256)
void softmax_kernel() {
    __shared__ float sh[8];
    const float* __restrict__ Srow = g_S + (size_t)blockIdx.x * NN;
    bf16* __restrict__ Prow = g_P + (size_t)blockIdx.x * NN;
    const int t = threadIdx.x;
    float4 v[4];
    float m = -3.4e38f;
    #pragma unroll
    for (int i = 0; i < 4; i++) {
        v[i] = ((const float4*)Srow)[t + i * 256];
        m = fmaxf(m, fmaxf(fmaxf(v[i].x, v[i].y), fmaxf(v[i].z, v[i].w)));
    }
    #pragma unroll
    for (int o = 16; o; o >>= 1) m = fmaxf(m, __shfl_xor_sync(~0u, m, o));
    if ((t & 31) == 0) sh[t >> 5] = m;
    __syncthreads();
    m = fmaxf(fmaxf(fmaxf(sh[0], sh[1]), fmaxf(sh[2], sh[3])),
              fmaxf(fmaxf(sh[4], sh[5]), fmaxf(sh[6], sh[7])));
    float s = 0.f;
    #pragma unroll
    for (int i = 0; i < 4; i++) {
        v[i].x = __expf(v[i].x - m); v[i].y = __expf(v[i].y - m);
        v[i].z = __expf(v[i].z - m); v[i].w = __expf(v[i].w - m);
        s += v[i].x + v[i].y + v[i].z + v[i].w;
    }
    #pragma unroll
    for (int o = 16; o; o >>= 1) s += __shfl_xor_sync(~0u, s, o);
    __syncthreads();
    if ((t & 31) == 0) sh[t >> 5] = s;
    __syncthreads();
    s = sh[0] + sh[1] + sh[2] + sh[3] + sh[4] + sh[5] + sh[6] + sh[7];
    const float inv = 1.0f / s;
    #pragma unroll
    for (int i = 0; i < 4; i++) {
        alignas(8) bf162 p[2];
        p[0] = __floats2bfloat162_rn(v[i].x * inv, v[i].y * inv);
        p[1] = __floats2bfloat162_rn(v[i].z * inv, v[i].w * inv);
        *(uint2*)&Prow[(size_t)(t + i * 256) * 4] = *(uint2*)&p[0];
    }
}

// ---------------- launch ------------------------------------------------------
extern "C" void kernel_launch(void* const* d_in, const int* in_sizes, int n_in,
                              void* d_out, int out_size) {
    const float* x      = (const float*)d_in[0];
    const float* gn_w   = (const float*)d_in[1];
    const float* gn_b   = (const float*)d_in[2];
    const float* q_w    = (const float*)d_in[3];
    const float* q_b    = (const float*)d_in[4];
    const float* k_w    = (const float*)d_in[5];
    const float* k_b    = (const float*)d_in[6];
    const float* v_w    = (const float*)d_in[7];
    const float* v_b    = (const float*)d_in[8];
    const float* proj_w = (const float*)d_in[9];
    const float* proj_b = (const float*)d_in[10];
    float* out = (float*)d_out;

    convert_w<<<1024, 256>>>(q_w, k_w, v_w, proj_w);
    groupnorm_kernel<<<BB * GRPS, 1024>>>(x, gn_w, gn_b);
    gemm_qk<<<dim3(CC / 128, NN / 128, 2 * BB), 256>>>(q_b, k_b);
    gemm_v<<<dim3(NN / 128, CC / 128, BB), 256>>>(v_b);
    const float scale = 0.044194173824159216f;   // 512^-0.5
    gemm_scores<<<dim3(NN / 128, NN / 128, BB), 256>>>(scale);
    softmax_kernel<<<BB * NN, 256>>>();
    gemm_out<<<dim3(CC / 128, NN / 128, BB), 256>>>();
    gemm_proj<<<dim3(CC / 128, NN / 128, BB), 256>>>(proj_b, x, out);
}